// round 11
// baseline (speedup 1.0000x reference)
#include <cuda_runtime.h>
#include <cuda_bf16.h>
#include <math.h>
#include <stdint.h>

#define DIM 256
#define INNER 768           // Q|K|V concatenated
#define HEADS 8
#define NMAX 50000
#define EMAX 800000

// ---------------- device scratch (static: allocation-free) --------------------
__device__ float          g_QKV[(size_t)NMAX * INNER];   // row: [q(256)|k(256)|v(256)]
__device__ __nv_bfloat16  g_xh[(size_t)NMAX * DIM];
__device__ __nv_bfloat16  g_xl[(size_t)NMAX * DIM];
__device__ __nv_bfloat16  g_wth[INNER * DIM];            // W^T hi: [n][k]
__device__ __nv_bfloat16  g_wtl[INNER * DIM];            // W^T lo
__device__ float          g_bf[INNER];
__device__ __align__(16) int g_deg[NMAX];
__device__ int            g_off[NMAX + 1];
__device__ int            g_cur[NMAX];
__device__ int            g_sperm[EMAX];   // src node id, permuted into dst-CSR order

__device__ __forceinline__ uint32_t smem_u32(const void* p) {
    uint32_t a;
    asm("{ .reg .u64 t; cvta.to.shared.u64 t, %1; cvt.u32.u64 %0, t; }" : "=r"(a) : "l"(p));
    return a;
}

// ---------------- prep: W^T hi/lo + bias --------------------------------------
__global__ void prep_w_kernel(const float* __restrict__ Wq, const float* __restrict__ bq,
                              const float* __restrict__ Wk, const float* __restrict__ bk,
                              const float* __restrict__ Wv, const float* __restrict__ bv) {
    int idx = blockIdx.x * blockDim.x + threadIdx.x;
    if (idx < INNER * DIM) {
        int n = idx >> 8, k = idx & 255;
        float w = (n < 256) ? Wq[k * 256 + n]
                : (n < 512) ? Wk[k * 256 + (n - 256)]
                            : Wv[k * 256 + (n - 512)];
        __nv_bfloat16 h = __float2bfloat16(w);
        __nv_bfloat16 l = __float2bfloat16(w - __bfloat162float(h));
        g_wth[idx] = h;   // layout [n][k] == idx
        g_wtl[idx] = l;
    }
    if (idx < INNER) {
        g_bf[idx] = (idx < 256) ? bq[idx] : (idx < 512) ? bk[idx - 256] : bv[idx - 512];
    }
}

__global__ void zero_deg_kernel(int n) {
    int i = blockIdx.x * blockDim.x + threadIdx.x;
    if (i < n) g_deg[i] = 0;
}

// ---------------- x -> bf16 hi/lo ----------------------------------------------
__global__ void conv_x_kernel(const float* __restrict__ x, int total4) {
    int i = blockIdx.x * blockDim.x + threadIdx.x;
    if (i >= total4) return;
    float4 v = ((const float4*)x)[i];
    float f[4] = {v.x, v.y, v.z, v.w};
    __nv_bfloat16 h[4], l[4];
#pragma unroll
    for (int j = 0; j < 4; ++j) {
        h[j] = __float2bfloat16(f[j]);
        l[j] = __float2bfloat16(f[j] - __bfloat162float(h[j]));
    }
    __nv_bfloat162* ph = (__nv_bfloat162*)g_xh + 2 * (size_t)i;
    __nv_bfloat162* pl = (__nv_bfloat162*)g_xl + 2 * (size_t)i;
    ph[0] = __halves2bfloat162(h[0], h[1]);
    ph[1] = __halves2bfloat162(h[2], h[3]);
    pl[0] = __halves2bfloat162(l[0], l[1]);
    pl[1] = __halves2bfloat162(l[2], l[3]);
}

// ---------------- mma.sync bf16 GEMM: g_QKV[M,768] = x @ W + b ----------------
// CTA 128x128, BK=32, 8 warps (2x4), warp tile 64x32.
// Split fp32: C = Ah*Bh + Ah*Bl + Al*Bh.  cp.async 2-stage pipeline.
#define BK 32
#define LDS 40            // smem row stride (bf16): 32 + 8 pad -> 80B
#define ARR_BYTES (128 * LDS * 2)      // 10240
#define OFF_AH 0
#define OFF_AL ARR_BYTES
#define OFF_BH (2 * ARR_BYTES)
#define OFF_BL (3 * ARR_BYTES)
#define STAGE_BYTES (4 * ARR_BYTES)    // 40960
#define GT_SMEM (2 * STAGE_BYTES)      // 81920

#define LDMX4(r0, r1, r2, r3, a)                                              \
    asm volatile("ldmatrix.sync.aligned.m8n8.x4.shared.b16 {%0,%1,%2,%3}, [%4];" \
        : "=r"(r0), "=r"(r1), "=r"(r2), "=r"(r3) : "r"(a))

#define MMA16816(c, A, B)                                                     \
    asm volatile("mma.sync.aligned.m16n8k16.row.col.f32.bf16.bf16.f32 "       \
        "{%0,%1,%2,%3}, {%4,%5,%6,%7}, {%8,%9}, {%0,%1,%2,%3};"               \
        : "+f"((c)[0]), "+f"((c)[1]), "+f"((c)[2]), "+f"((c)[3])              \
        : "r"((A)[0]), "r"((A)[1]), "r"((A)[2]), "r"((A)[3]),                 \
          "r"((B)[0]), "r"((B)[1]))

__device__ __forceinline__ void cp16(uint32_t d, const void* s, int sz) {
    asm volatile("cp.async.cg.shared.global [%0], [%1], 16, %2;"
                 :: "r"(d), "l"(s), "r"(sz));
}
#define CP_COMMIT() asm volatile("cp.async.commit_group;" ::: "memory")
#define CP_WAIT1()  asm volatile("cp.async.wait_group 1;" ::: "memory")

__global__ __launch_bounds__(256) void gemm_mma_kernel(int Nn) {
    extern __shared__ __align__(16) char dynsmem[];

    const int t = threadIdx.x;
    const int lane = t & 31;
    const int w = t >> 5;
    const int wm = (w & 1) * 64;     // warp row offset in CTA tile
    const int wn = (w >> 1) * 32;    // warp col offset
    const int m0 = blockIdx.x * 128;
    const int n0 = blockIdx.y * 128;
    const uint32_t sbase = smem_u32(dynsmem);

    float acc[4][4][4];
#pragma unroll
    for (int i = 0; i < 4; ++i)
#pragma unroll
        for (int j = 0; j < 4; ++j)
#pragma unroll
            for (int c = 0; c < 4; ++c) acc[i][j][c] = 0.f;

    // gmem->smem indices: 2 threads per row, 16 bf16 (32B = 2 cp.async) each
    const int ldr = t >> 1;               // 0..127
    const int ldc = (t & 1) * 16;         // 0 or 16
    const int s_byte = (ldr * LDS + ldc) * 2;
    const int asz = ((m0 + ldr) < Nn) ? 16 : 0;   // zero-fill M tail

    const __nv_bfloat16* gah = g_xh  + (size_t)(m0 + ldr) * DIM + ldc;
    const __nv_bfloat16* gal = g_xl  + (size_t)(m0 + ldr) * DIM + ldc;
    const __nv_bfloat16* gbh = g_wth + (size_t)(n0 + ldr) * DIM + ldc;
    const __nv_bfloat16* gbl = g_wtl + (size_t)(n0 + ldr) * DIM + ldc;

#define LOAD_STAGE(stg, k0) do {                                              \
        uint32_t sb_ = sbase + (stg) * STAGE_BYTES;                           \
        cp16(sb_ + OFF_AH + s_byte,      gah + (k0),     asz);                \
        cp16(sb_ + OFF_AH + s_byte + 16, gah + (k0) + 8, asz);                \
        cp16(sb_ + OFF_AL + s_byte,      gal + (k0),     asz);                \
        cp16(sb_ + OFF_AL + s_byte + 16, gal + (k0) + 8, asz);                \
        cp16(sb_ + OFF_BH + s_byte,      gbh + (k0),     16);                 \
        cp16(sb_ + OFF_BH + s_byte + 16, gbh + (k0) + 8, 16);                 \
        cp16(sb_ + OFF_BL + s_byte,      gbl + (k0),     16);                 \
        cp16(sb_ + OFF_BL + s_byte + 16, gbl + (k0) + 8, 16);                 \
    } while (0)

    LOAD_STAGE(0, 0);
    CP_COMMIT();

#pragma unroll 1
    for (int it = 0; it < DIM / BK; ++it) {
        if (it + 1 < DIM / BK) LOAD_STAGE((it + 1) & 1, (it + 1) * BK);
        CP_COMMIT();
        CP_WAIT1();
        __syncthreads();

        const uint32_t stg = sbase + (it & 1) * STAGE_BYTES;
        const uint32_t ah_b = stg + OFF_AH, al_b = stg + OFF_AL;
        const uint32_t bh_b = stg + OFF_BH, bl_b = stg + OFF_BL;

#pragma unroll
        for (int kk = 0; kk < BK; kk += 16) {
            // A fragments: 4 m-tiles x (hi, lo)
            uint32_t ah[4][4], al[4][4];
            {
                uint32_t aoff = ((wm + (lane & 15)) * LDS + kk + (lane >> 4) * 8) * 2;
#pragma unroll
                for (int mt = 0; mt < 4; ++mt) {
                    uint32_t adr = aoff + mt * 16 * LDS * 2;
                    LDMX4(ah[mt][0], ah[mt][1], ah[mt][2], ah[mt][3], ah_b + adr);
                    LDMX4(al[mt][0], al[mt][1], al[mt][2], al[mt][3], al_b + adr);
                }
            }
            // B fragments: 4 n-tiles x (hi, lo); x4 loads cover 2 n-tiles each
            uint32_t bh[4][2], bl[4][2];
            {
                int g = lane >> 3;
                uint32_t boff = ((wn + (g >> 1) * 8 + (lane & 7)) * LDS + kk + (g & 1) * 8) * 2;
#pragma unroll
                for (int p = 0; p < 2; ++p) {
                    uint32_t adr = boff + p * 16 * LDS * 2;
                    LDMX4(bh[2 * p][0], bh[2 * p][1], bh[2 * p + 1][0], bh[2 * p + 1][1], bh_b + adr);
                    LDMX4(bl[2 * p][0], bl[2 * p][1], bl[2 * p + 1][0], bl[2 * p + 1][1], bl_b + adr);
                }
            }
#pragma unroll
            for (int mt = 0; mt < 4; ++mt)
#pragma unroll
                for (int nt = 0; nt < 4; ++nt) {
                    MMA16816(acc[mt][nt], ah[mt], bh[nt]);
                    MMA16816(acc[mt][nt], ah[mt], bl[nt]);
                    MMA16816(acc[mt][nt], al[mt], bh[nt]);
                }
        }
        __syncthreads();
    }

    // epilogue: + bias, store float2 per fragment half
#pragma unroll
    for (int mt = 0; mt < 4; ++mt) {
#pragma unroll
        for (int nt = 0; nt < 4; ++nt) {
            int row = m0 + wm + mt * 16 + (lane >> 2);
            int col = n0 + wn + nt * 8 + (lane & 3) * 2;
            float2 bv = *(const float2*)(g_bf + col);
            if (row < Nn) {
                float2 o; o.x = acc[mt][nt][0] + bv.x; o.y = acc[mt][nt][1] + bv.y;
                *(float2*)(g_QKV + (size_t)row * INNER + col) = o;
            }
            if (row + 8 < Nn) {
                float2 o; o.x = acc[mt][nt][2] + bv.x; o.y = acc[mt][nt][3] + bv.y;
                *(float2*)(g_QKV + (size_t)(row + 8) * INNER + col) = o;
            }
        }
    }
}

// ---------------- CSR build ----------------------------------------------------
__global__ void hist_kernel(const int* __restrict__ dst, int E) {
    int e = blockIdx.x * blockDim.x + threadIdx.x;
    if (e < E) atomicAdd(&g_deg[dst[e]], 1);
}

// single-block shuffle-based exclusive scan: 1024 threads x 4 elements/tile
__global__ __launch_bounds__(1024) void scan_kernel(int n) {
    __shared__ int wsum[32];
    __shared__ int carry_s;
    const int t = threadIdx.x, lane = t & 31, wid = t >> 5;
    if (t == 0) carry_s = 0;
    __syncthreads();
    const int nTiles = (n + 4095) >> 12;
    for (int tile = 0; tile < nTiles; ++tile) {
        int idx = (tile << 12) + t * 4;
        int4 v = make_int4(0, 0, 0, 0);
        if (idx + 3 < n) v = *(const int4*)(g_deg + idx);
        else {
            if (idx + 0 < n) v.x = g_deg[idx];
            if (idx + 1 < n) v.y = g_deg[idx + 1];
            if (idx + 2 < n) v.z = g_deg[idx + 2];
        }
        int s = v.x + v.y + v.z + v.w;
        int incl = s;
#pragma unroll
        for (int d = 1; d < 32; d <<= 1) {
            int o = __shfl_up_sync(0xffffffffu, incl, d);
            if (lane >= d) incl += o;
        }
        if (lane == 31) wsum[wid] = incl;
        __syncthreads();
        if (wid == 0) {
            int ws = wsum[lane];
            int wincl = ws;
#pragma unroll
            for (int d = 1; d < 32; d <<= 1) {
                int o = __shfl_up_sync(0xffffffffu, wincl, d);
                if (lane >= d) wincl += o;
            }
            wsum[lane] = wincl - ws;   // exclusive warp prefix
        }
        __syncthreads();
        int excl = carry_s + wsum[wid] + (incl - s);
        int e0 = excl, e1 = e0 + v.x, e2 = e1 + v.y, e3 = e2 + v.z;
        if (idx + 0 < n) { g_off[idx + 0] = e0; g_cur[idx + 0] = e0; }
        if (idx + 1 < n) { g_off[idx + 1] = e1; g_cur[idx + 1] = e1; }
        if (idx + 2 < n) { g_off[idx + 2] = e2; g_cur[idx + 2] = e2; }
        if (idx + 3 < n) { g_off[idx + 3] = e3; g_cur[idx + 3] = e3; }
        __syncthreads();
        if (t == 1023) carry_s += wsum[31] + incl;
        __syncthreads();
    }
    if (t == 0) g_off[n] = carry_s;
}

// store src node id directly (kills one indirection in the attention hot loop)
__global__ void scatter_kernel(const int* __restrict__ dst, const int* __restrict__ src,
                               int E) {
    int e = blockIdx.x * blockDim.x + threadIdx.x;
    if (e < E) {
        int p = atomicAdd(&g_cur[dst[e]], 1);
        g_sperm[p] = src[e];
    }
}

// ---------------- single-pass online-softmax attention ------------------------
// one warp per dst node; lane l owns output dims [8l,8l+8); head = l>>2.
__global__ __launch_bounds__(256) void attn_kernel(float* __restrict__ out, int n_nodes) {
    int gwarp = (blockIdx.x * blockDim.x + threadIdx.x) >> 5;
    int lane = threadIdx.x & 31;
    if (gwarp >= n_nodes) return;
    const int rs = g_off[gwarp];
    const int re = g_off[gwarp + 1];

    const float4* kp = (const float4*)(g_QKV + (size_t)gwarp * INNER + 256 + lane * 8);
    const float4 k0 = kp[0], k1 = kp[1];

    float m = -INFINITY, z = 0.f;
    float4 a0 = make_float4(0.f, 0.f, 0.f, 0.f);
    float4 a1 = make_float4(0.f, 0.f, 0.f, 0.f);

    // prefetch first index: the index load heads the dependent chain
    int s = (rs < re) ? __ldg(&g_sperm[rs]) : 0;

    for (int i = rs; i < re; ++i) {
        int s_next = (i + 1 < re) ? __ldg(&g_sperm[i + 1]) : 0;

        const float4* qp = (const float4*)(g_QKV + (size_t)s * INNER + lane * 8);
        const float4* vp = (const float4*)(g_QKV + (size_t)s * INNER + 512 + lane * 8);
        float4 q0 = qp[0], q1 = qp[1];
        float4 v0 = vp[0], v1 = vp[1];

        float p = q0.x * k0.x + q0.y * k0.y + q0.z * k0.z + q0.w * k0.w
                + q1.x * k1.x + q1.y * k1.y + q1.z * k1.z + q1.w * k1.w;
        p += __shfl_xor_sync(0xffffffffu, p, 1);
        p += __shfl_xor_sync(0xffffffffu, p, 2);
        float sc = p * 0.17677669529663689f;   // 1/sqrt(32)

        float nm = fmaxf(m, sc);
        float scale = __expf(m - nm);          // first iter: exp(-inf)=0
        float wgt = __expf(sc - nm);
        m = nm;
        z = fmaf(z, scale, wgt);
        a0.x = fmaf(a0.x, scale, v0.x * wgt); a0.y = fmaf(a0.y, scale, v0.y * wgt);
        a0.z = fmaf(a0.z, scale, v0.z * wgt); a0.w = fmaf(a0.w, scale, v0.w * wgt);
        a1.x = fmaf(a1.x, scale, v1.x * wgt); a1.y = fmaf(a1.y, scale, v1.y * wgt);
        a1.z = fmaf(a1.z, scale, v1.z * wgt); a1.w = fmaf(a1.w, scale, v1.w * wgt);

        s = s_next;
    }
    float inv = 1.f / fmaxf(z, 1e-16f);
    float4* op = (float4*)(out + (size_t)gwarp * 256 + lane * 8);
    op[0] = make_float4(a0.x * inv, a0.y * inv, a0.z * inv, a0.w * inv);
    op[1] = make_float4(a1.x * inv, a1.y * inv, a1.z * inv, a1.w * inv);
}

// ---------------- launch: two-stream fork/join ---------------------------------
// DAG:  prep_w ─┐                 conv_x ─┐
//               ├─> gemm ──┐              │  (conv_x on side stream, own event)
//               ┘          ├─> attn       │
//   zero->hist->scan->scatter ──┘ (side)  │
// Submission order puts gemm 6th so ncu (-s 5 -c 1) samples it.
extern "C" void kernel_launch(void* const* d_in, const int* in_sizes, int n_in,
                              void* d_out, int out_size) {
    const float* x  = (const float*)d_in[0];
    const float* Wq = (const float*)d_in[1];
    const float* bq = (const float*)d_in[2];
    const float* Wk = (const float*)d_in[3];
    const float* bk = (const float*)d_in[4];
    const float* Wv = (const float*)d_in[5];
    const float* bv = (const float*)d_in[6];
    const int* src  = (const int*)d_in[7];
    const int* dst  = (const int*)d_in[8];
    float* out = (float*)d_out;

    const int N = in_sizes[0] / DIM;
    const int E = in_sizes[7];

    // one-time host-side resources (no device memory involved)
    static cudaStream_t s_side = nullptr;
    static cudaEvent_t  s_evFork = nullptr, s_evConv = nullptr, s_evJoin = nullptr;
    static bool s_attrSet = false;
    if (s_side == nullptr) {
        cudaStreamCreateWithFlags(&s_side, cudaStreamNonBlocking);
        cudaEventCreateWithFlags(&s_evFork, cudaEventDisableTiming);
        cudaEventCreateWithFlags(&s_evConv, cudaEventDisableTiming);
        cudaEventCreateWithFlags(&s_evJoin, cudaEventDisableTiming);
    }
    if (!s_attrSet) {
        cudaFuncSetAttribute(gemm_mma_kernel,
                             cudaFuncAttributeMaxDynamicSharedMemorySize, GT_SMEM);
        s_attrSet = true;
    }

    // fork: side stream picks up from the capture/default stream
    cudaEventRecord(s_evFork, 0);
    cudaStreamWaitEvent(s_side, s_evFork, 0);

    // (1) chain A: weight prep
    prep_w_kernel<<<(INNER * DIM + 255) / 256, 256>>>(Wq, bq, Wk, bk, Wv, bv);

    // (2) side: x -> bf16 hi/lo, then its own completion event
    conv_x_kernel<<<(N * (DIM / 4) + 255) / 256, 256, 0, s_side>>>(x, N * (DIM / 4));
    cudaEventRecord(s_evConv, s_side);

    // (3-5) side: CSR by dst (zero -> hist -> scan)
    zero_deg_kernel<<<(N + 255) / 256, 256, 0, s_side>>>(N);
    hist_kernel<<<(E + 255) / 256, 256, 0, s_side>>>(dst, E);
    scan_kernel<<<1, 1024, 0, s_side>>>(N);

    // (6) chain A: GEMM (waits for conv_x via event; prep_w same-stream)
    cudaStreamWaitEvent(0, s_evConv, 0);
    dim3 ggrid((N + 127) / 128, INNER / 128);
    gemm_mma_kernel<<<ggrid, 256, GT_SMEM>>>(N);

    // (7) side: scatter completes the CSR chain
    scatter_kernel<<<(E + 255) / 256, 256, 0, s_side>>>(dst, src, E);
    cudaEventRecord(s_evJoin, s_side);

    // (8) join, then attention
    cudaStreamWaitEvent(0, s_evJoin, 0);
    attn_kernel<<<(N + 7) / 8, 256>>>(out, N);
}

// round 14
// speedup vs baseline: 1.1252x; 1.1252x over previous
#include <cuda_runtime.h>
#include <cuda_bf16.h>
#include <math.h>
#include <stdint.h>

#define DIM 256
#define INNER 768           // Q|K|V concatenated
#define HEADS 8
#define NMAX 50000
#define EMAX 800000

// ---------------- device scratch (static: allocation-free) --------------------
__device__ float          g_QKV[(size_t)NMAX * INNER];   // row: [q(256)|k(256)|v(256)]
__device__ __nv_bfloat16  g_xh[(size_t)NMAX * DIM];
__device__ __nv_bfloat16  g_xl[(size_t)NMAX * DIM];
__device__ __nv_bfloat16  g_wth[INNER * DIM];            // W^T hi: [n][k]
__device__ __nv_bfloat16  g_wtl[INNER * DIM];            // W^T lo
__device__ float          g_bf[INNER];
__device__ __align__(16) int g_deg[NMAX];
__device__ int            g_off[NMAX + 1];
__device__ int            g_cur[NMAX];
__device__ int            g_sperm[EMAX];   // src node id, permuted into dst-CSR order

__device__ __forceinline__ uint32_t smem_u32(const void* p) {
    uint32_t a;
    asm("{ .reg .u64 t; cvta.to.shared.u64 t, %1; cvt.u32.u64 %0, t; }" : "=r"(a) : "l"(p));
    return a;
}

// ---------------- prep: W^T hi/lo + bias --------------------------------------
__global__ void prep_w_kernel(const float* __restrict__ Wq, const float* __restrict__ bq,
                              const float* __restrict__ Wk, const float* __restrict__ bk,
                              const float* __restrict__ Wv, const float* __restrict__ bv) {
    int idx = blockIdx.x * blockDim.x + threadIdx.x;
    if (idx < INNER * DIM) {
        int n = idx >> 8, k = idx & 255;
        float w = (n < 256) ? Wq[k * 256 + n]
                : (n < 512) ? Wk[k * 256 + (n - 256)]
                            : Wv[k * 256 + (n - 512)];
        __nv_bfloat16 h = __float2bfloat16(w);
        __nv_bfloat16 l = __float2bfloat16(w - __bfloat162float(h));
        g_wth[idx] = h;   // layout [n][k] == idx
        g_wtl[idx] = l;
    }
    if (idx < INNER) {
        g_bf[idx] = (idx < 256) ? bq[idx] : (idx < 512) ? bk[idx - 256] : bv[idx - 512];
    }
}

__global__ void zero_deg_kernel(int n) {
    int i = blockIdx.x * blockDim.x + threadIdx.x;
    if (i < n) g_deg[i] = 0;
}

// ---------------- x -> bf16 hi/lo ----------------------------------------------
__global__ void conv_x_kernel(const float* __restrict__ x, int total4) {
    int i = blockIdx.x * blockDim.x + threadIdx.x;
    if (i >= total4) return;
    float4 v = ((const float4*)x)[i];
    float f[4] = {v.x, v.y, v.z, v.w};
    __nv_bfloat16 h[4], l[4];
#pragma unroll
    for (int j = 0; j < 4; ++j) {
        h[j] = __float2bfloat16(f[j]);
        l[j] = __float2bfloat16(f[j] - __bfloat162float(h[j]));
    }
    __nv_bfloat162* ph = (__nv_bfloat162*)g_xh + 2 * (size_t)i;
    __nv_bfloat162* pl = (__nv_bfloat162*)g_xl + 2 * (size_t)i;
    ph[0] = __halves2bfloat162(h[0], h[1]);
    ph[1] = __halves2bfloat162(h[2], h[3]);
    pl[0] = __halves2bfloat162(l[0], l[1]);
    pl[1] = __halves2bfloat162(l[2], l[3]);
}

// ---------------- mma.sync bf16 GEMM: g_QKV[M,768] = x @ W + b ----------------
// CTA 128x128, BK=32, 8 warps (2x4), warp tile 64x32.
// Split fp32: C = Ah*Bh + Ah*Bl + Al*Bh.  cp.async 2-stage pipeline.
#define BK 32
#define LDS 40            // smem row stride (bf16): 32 + 8 pad -> 80B
#define ARR_BYTES (128 * LDS * 2)      // 10240
#define OFF_AH 0
#define OFF_AL ARR_BYTES
#define OFF_BH (2 * ARR_BYTES)
#define OFF_BL (3 * ARR_BYTES)
#define STAGE_BYTES (4 * ARR_BYTES)    // 40960
#define GT_SMEM (2 * STAGE_BYTES)      // 81920

#define LDMX4(r0, r1, r2, r3, a)                                              \
    asm volatile("ldmatrix.sync.aligned.m8n8.x4.shared.b16 {%0,%1,%2,%3}, [%4];" \
        : "=r"(r0), "=r"(r1), "=r"(r2), "=r"(r3) : "r"(a))

#define MMA16816(c, A, B)                                                     \
    asm volatile("mma.sync.aligned.m16n8k16.row.col.f32.bf16.bf16.f32 "       \
        "{%0,%1,%2,%3}, {%4,%5,%6,%7}, {%8,%9}, {%0,%1,%2,%3};"               \
        : "+f"((c)[0]), "+f"((c)[1]), "+f"((c)[2]), "+f"((c)[3])              \
        : "r"((A)[0]), "r"((A)[1]), "r"((A)[2]), "r"((A)[3]),                 \
          "r"((B)[0]), "r"((B)[1]))

__device__ __forceinline__ void cp16(uint32_t d, const void* s, int sz) {
    asm volatile("cp.async.cg.shared.global [%0], [%1], 16, %2;"
                 :: "r"(d), "l"(s), "r"(sz));
}
#define CP_COMMIT() asm volatile("cp.async.commit_group;" ::: "memory")
#define CP_WAIT1()  asm volatile("cp.async.wait_group 1;" ::: "memory")

__global__ __launch_bounds__(256) void gemm_mma_kernel(int Nn) {
    extern __shared__ __align__(16) char dynsmem[];

    const int t = threadIdx.x;
    const int lane = t & 31;
    const int w = t >> 5;
    const int wm = (w & 1) * 64;     // warp row offset in CTA tile
    const int wn = (w >> 1) * 32;    // warp col offset
    const int m0 = blockIdx.x * 128;
    const int n0 = blockIdx.y * 128;
    const uint32_t sbase = smem_u32(dynsmem);

    float acc[4][4][4];
#pragma unroll
    for (int i = 0; i < 4; ++i)
#pragma unroll
        for (int j = 0; j < 4; ++j)
#pragma unroll
            for (int c = 0; c < 4; ++c) acc[i][j][c] = 0.f;

    // gmem->smem indices: 2 threads per row, 16 bf16 (32B = 2 cp.async) each
    const int ldr = t >> 1;               // 0..127
    const int ldc = (t & 1) * 16;         // 0 or 16
    const int s_byte = (ldr * LDS + ldc) * 2;
    const int asz = ((m0 + ldr) < Nn) ? 16 : 0;   // zero-fill M tail

    const __nv_bfloat16* gah = g_xh  + (size_t)(m0 + ldr) * DIM + ldc;
    const __nv_bfloat16* gal = g_xl  + (size_t)(m0 + ldr) * DIM + ldc;
    const __nv_bfloat16* gbh = g_wth + (size_t)(n0 + ldr) * DIM + ldc;
    const __nv_bfloat16* gbl = g_wtl + (size_t)(n0 + ldr) * DIM + ldc;

#define LOAD_STAGE(stg, k0) do {                                              \
        uint32_t sb_ = sbase + (stg) * STAGE_BYTES;                           \
        cp16(sb_ + OFF_AH + s_byte,      gah + (k0),     asz);                \
        cp16(sb_ + OFF_AH + s_byte + 16, gah + (k0) + 8, asz);                \
        cp16(sb_ + OFF_AL + s_byte,      gal + (k0),     asz);                \
        cp16(sb_ + OFF_AL + s_byte + 16, gal + (k0) + 8, asz);                \
        cp16(sb_ + OFF_BH + s_byte,      gbh + (k0),     16);                 \
        cp16(sb_ + OFF_BH + s_byte + 16, gbh + (k0) + 8, 16);                 \
        cp16(sb_ + OFF_BL + s_byte,      gbl + (k0),     16);                 \
        cp16(sb_ + OFF_BL + s_byte + 16, gbl + (k0) + 8, 16);                 \
    } while (0)

    LOAD_STAGE(0, 0);
    CP_COMMIT();

#pragma unroll 1
    for (int it = 0; it < DIM / BK; ++it) {
        if (it + 1 < DIM / BK) LOAD_STAGE((it + 1) & 1, (it + 1) * BK);
        CP_COMMIT();
        CP_WAIT1();
        __syncthreads();

        const uint32_t stg = sbase + (it & 1) * STAGE_BYTES;
        const uint32_t ah_b = stg + OFF_AH, al_b = stg + OFF_AL;
        const uint32_t bh_b = stg + OFF_BH, bl_b = stg + OFF_BL;

#pragma unroll
        for (int kk = 0; kk < BK; kk += 16) {
            // A fragments: 4 m-tiles x (hi, lo)
            uint32_t ah[4][4], al[4][4];
            {
                uint32_t aoff = ((wm + (lane & 15)) * LDS + kk + (lane >> 4) * 8) * 2;
#pragma unroll
                for (int mt = 0; mt < 4; ++mt) {
                    uint32_t adr = aoff + mt * 16 * LDS * 2;
                    LDMX4(ah[mt][0], ah[mt][1], ah[mt][2], ah[mt][3], ah_b + adr);
                    LDMX4(al[mt][0], al[mt][1], al[mt][2], al[mt][3], al_b + adr);
                }
            }
            // B fragments: 4 n-tiles x (hi, lo); x4 loads cover 2 n-tiles each
            uint32_t bh[4][2], bl[4][2];
            {
                int g = lane >> 3;
                uint32_t boff = ((wn + (g >> 1) * 8 + (lane & 7)) * LDS + kk + (g & 1) * 8) * 2;
#pragma unroll
                for (int p = 0; p < 2; ++p) {
                    uint32_t adr = boff + p * 16 * LDS * 2;
                    LDMX4(bh[2 * p][0], bh[2 * p][1], bh[2 * p + 1][0], bh[2 * p + 1][1], bh_b + adr);
                    LDMX4(bl[2 * p][0], bl[2 * p][1], bl[2 * p + 1][0], bl[2 * p + 1][1], bl_b + adr);
                }
            }
#pragma unroll
            for (int mt = 0; mt < 4; ++mt)
#pragma unroll
                for (int nt = 0; nt < 4; ++nt) {
                    MMA16816(acc[mt][nt], ah[mt], bh[nt]);
                    MMA16816(acc[mt][nt], ah[mt], bl[nt]);
                    MMA16816(acc[mt][nt], al[mt], bh[nt]);
                }
        }
        __syncthreads();
    }

    // epilogue: + bias, store float2 per fragment half
#pragma unroll
    for (int mt = 0; mt < 4; ++mt) {
#pragma unroll
        for (int nt = 0; nt < 4; ++nt) {
            int row = m0 + wm + mt * 16 + (lane >> 2);
            int col = n0 + wn + nt * 8 + (lane & 3) * 2;
            float2 bv = *(const float2*)(g_bf + col);
            if (row < Nn) {
                float2 o; o.x = acc[mt][nt][0] + bv.x; o.y = acc[mt][nt][1] + bv.y;
                *(float2*)(g_QKV + (size_t)row * INNER + col) = o;
            }
            if (row + 8 < Nn) {
                float2 o; o.x = acc[mt][nt][2] + bv.x; o.y = acc[mt][nt][3] + bv.y;
                *(float2*)(g_QKV + (size_t)(row + 8) * INNER + col) = o;
            }
        }
    }
}

// ---------------- CSR build ----------------------------------------------------
__global__ void hist_kernel(const int* __restrict__ dst, int E) {
    int e = blockIdx.x * blockDim.x + threadIdx.x;
    if (e < E) atomicAdd(&g_deg[dst[e]], 1);
}

// single-block shuffle-based exclusive scan: 1024 threads x 4 elements/tile
__global__ __launch_bounds__(1024) void scan_kernel(int n) {
    __shared__ int wsum[32];
    __shared__ int carry_s;
    const int t = threadIdx.x, lane = t & 31, wid = t >> 5;
    if (t == 0) carry_s = 0;
    __syncthreads();
    const int nTiles = (n + 4095) >> 12;
    for (int tile = 0; tile < nTiles; ++tile) {
        int idx = (tile << 12) + t * 4;
        int4 v = make_int4(0, 0, 0, 0);
        if (idx + 3 < n) v = *(const int4*)(g_deg + idx);
        else {
            if (idx + 0 < n) v.x = g_deg[idx];
            if (idx + 1 < n) v.y = g_deg[idx + 1];
            if (idx + 2 < n) v.z = g_deg[idx + 2];
        }
        int s = v.x + v.y + v.z + v.w;
        int incl = s;
#pragma unroll
        for (int d = 1; d < 32; d <<= 1) {
            int o = __shfl_up_sync(0xffffffffu, incl, d);
            if (lane >= d) incl += o;
        }
        if (lane == 31) wsum[wid] = incl;
        __syncthreads();
        if (wid == 0) {
            int ws = wsum[lane];
            int wincl = ws;
#pragma unroll
            for (int d = 1; d < 32; d <<= 1) {
                int o = __shfl_up_sync(0xffffffffu, wincl, d);
                if (lane >= d) wincl += o;
            }
            wsum[lane] = wincl - ws;   // exclusive warp prefix
        }
        __syncthreads();
        int excl = carry_s + wsum[wid] + (incl - s);
        int e0 = excl, e1 = e0 + v.x, e2 = e1 + v.y, e3 = e2 + v.z;
        if (idx + 0 < n) { g_off[idx + 0] = e0; g_cur[idx + 0] = e0; }
        if (idx + 1 < n) { g_off[idx + 1] = e1; g_cur[idx + 1] = e1; }
        if (idx + 2 < n) { g_off[idx + 2] = e2; g_cur[idx + 2] = e2; }
        if (idx + 3 < n) { g_off[idx + 3] = e3; g_cur[idx + 3] = e3; }
        __syncthreads();
        if (t == 1023) carry_s += wsum[31] + incl;
        __syncthreads();
    }
    if (t == 0) g_off[n] = carry_s;
}

// store src node id directly (kills one indirection in the attention hot loop)
__global__ void scatter_kernel(const int* __restrict__ dst, const int* __restrict__ src,
                               int E) {
    int e = blockIdx.x * blockDim.x + threadIdx.x;
    if (e < E) {
        int p = atomicAdd(&g_cur[dst[e]], 1);
        g_sperm[p] = src[e];
    }
}

// ---------------- single-pass online-softmax attention (2x unrolled) ----------
// one warp per dst node; lane l owns output dims [8l,8l+8); head = l>>2.
__global__ __launch_bounds__(256) void attn_kernel(float* __restrict__ out, int n_nodes) {
    int gwarp = (blockIdx.x * blockDim.x + threadIdx.x) >> 5;
    int lane = threadIdx.x & 31;
    if (gwarp >= n_nodes) return;
    const int rs = g_off[gwarp];
    const int re = g_off[gwarp + 1];

    const float4* kp = (const float4*)(g_QKV + (size_t)gwarp * INNER + 256 + lane * 8);
    const float4 k0 = kp[0], k1 = kp[1];

    float m = -INFINITY, z = 0.f;
    float4 a0 = make_float4(0.f, 0.f, 0.f, 0.f);
    float4 a1 = make_float4(0.f, 0.f, 0.f, 0.f);

    int i = rs;
    // pairwise loop: 8 LDG.128 in flight, one serial softmax-rescale per pair
    for (; i + 1 < re; i += 2) {
        int s0 = __ldg(&g_sperm[i]);
        int s1 = __ldg(&g_sperm[i + 1]);
        const float* b0 = g_QKV + (size_t)s0 * INNER + lane * 8;
        const float* b1 = g_QKV + (size_t)s1 * INNER + lane * 8;
        float4 q00 = *(const float4*)(b0);
        float4 q01 = *(const float4*)(b0 + 4);
        float4 q10 = *(const float4*)(b1);
        float4 q11 = *(const float4*)(b1 + 4);
        float4 v00 = *(const float4*)(b0 + 512);
        float4 v01 = *(const float4*)(b0 + 516);
        float4 v10 = *(const float4*)(b1 + 512);
        float4 v11 = *(const float4*)(b1 + 516);

        float p0 = q00.x * k0.x + q00.y * k0.y + q00.z * k0.z + q00.w * k0.w
                 + q01.x * k1.x + q01.y * k1.y + q01.z * k1.z + q01.w * k1.w;
        float p1 = q10.x * k0.x + q10.y * k0.y + q10.z * k0.z + q10.w * k0.w
                 + q11.x * k1.x + q11.y * k1.y + q11.z * k1.z + q11.w * k1.w;
        p0 += __shfl_xor_sync(0xffffffffu, p0, 1);
        p1 += __shfl_xor_sync(0xffffffffu, p1, 1);
        p0 += __shfl_xor_sync(0xffffffffu, p0, 2);
        p1 += __shfl_xor_sync(0xffffffffu, p1, 2);
        float sc0 = p0 * 0.17677669529663689f;   // 1/sqrt(32)
        float sc1 = p1 * 0.17677669529663689f;

        float nm = fmaxf(m, fmaxf(sc0, sc1));
        float scale = __expf(m - nm);            // first pair: exp(-inf)=0
        float w0 = __expf(sc0 - nm);
        float w1 = __expf(sc1 - nm);
        m = nm;
        z = fmaf(z, scale, w0 + w1);
        a0.x = fmaf(a0.x, scale, fmaf(v00.x, w0, v10.x * w1));
        a0.y = fmaf(a0.y, scale, fmaf(v00.y, w0, v10.y * w1));
        a0.z = fmaf(a0.z, scale, fmaf(v00.z, w0, v10.z * w1));
        a0.w = fmaf(a0.w, scale, fmaf(v00.w, w0, v10.w * w1));
        a1.x = fmaf(a1.x, scale, fmaf(v01.x, w0, v11.x * w1));
        a1.y = fmaf(a1.y, scale, fmaf(v01.y, w0, v11.y * w1));
        a1.z = fmaf(a1.z, scale, fmaf(v01.z, w0, v11.z * w1));
        a1.w = fmaf(a1.w, scale, fmaf(v01.w, w0, v11.w * w1));
    }
    // tail edge (odd degree)
    if (i < re) {
        int s = __ldg(&g_sperm[i]);
        const float* b = g_QKV + (size_t)s * INNER + lane * 8;
        float4 q0 = *(const float4*)(b);
        float4 q1 = *(const float4*)(b + 4);
        float4 v0 = *(const float4*)(b + 512);
        float4 v1 = *(const float4*)(b + 516);

        float p = q0.x * k0.x + q0.y * k0.y + q0.z * k0.z + q0.w * k0.w
                + q1.x * k1.x + q1.y * k1.y + q1.z * k1.z + q1.w * k1.w;
        p += __shfl_xor_sync(0xffffffffu, p, 1);
        p += __shfl_xor_sync(0xffffffffu, p, 2);
        float sc = p * 0.17677669529663689f;

        float nm = fmaxf(m, sc);
        float scale = __expf(m - nm);
        float wgt = __expf(sc - nm);
        m = nm;
        z = fmaf(z, scale, wgt);
        a0.x = fmaf(a0.x, scale, v0.x * wgt); a0.y = fmaf(a0.y, scale, v0.y * wgt);
        a0.z = fmaf(a0.z, scale, v0.z * wgt); a0.w = fmaf(a0.w, scale, v0.w * wgt);
        a1.x = fmaf(a1.x, scale, v1.x * wgt); a1.y = fmaf(a1.y, scale, v1.y * wgt);
        a1.z = fmaf(a1.z, scale, v1.z * wgt); a1.w = fmaf(a1.w, scale, v1.w * wgt);
    }

    float inv = 1.f / fmaxf(z, 1e-16f);
    float4* op = (float4*)(out + (size_t)gwarp * 256 + lane * 8);
    op[0] = make_float4(a0.x * inv, a0.y * inv, a0.z * inv, a0.w * inv);
    op[1] = make_float4(a1.x * inv, a1.y * inv, a1.z * inv, a1.w * inv);
}

// ---------------- launch: two-stream fork/join (R10 structure) -----------------
// Chain A (default stream): prep_w -> conv_x -> gemm        (feeds attn)
// Chain B (side stream):    zero_deg -> hist -> scan -> scatter (feeds attn)
extern "C" void kernel_launch(void* const* d_in, const int* in_sizes, int n_in,
                              void* d_out, int out_size) {
    const float* x  = (const float*)d_in[0];
    const float* Wq = (const float*)d_in[1];
    const float* bq = (const float*)d_in[2];
    const float* Wk = (const float*)d_in[3];
    const float* bk = (const float*)d_in[4];
    const float* Wv = (const float*)d_in[5];
    const float* bv = (const float*)d_in[6];
    const int* src  = (const int*)d_in[7];
    const int* dst  = (const int*)d_in[8];
    float* out = (float*)d_out;

    const int N = in_sizes[0] / DIM;
    const int E = in_sizes[7];

    // one-time host-side resources (no device memory involved)
    static cudaStream_t s_side = nullptr;
    static cudaEvent_t  s_evFork = nullptr, s_evJoin = nullptr;
    static bool s_attrSet = false;
    if (s_side == nullptr) {
        cudaStreamCreateWithFlags(&s_side, cudaStreamNonBlocking);
        cudaEventCreateWithFlags(&s_evFork, cudaEventDisableTiming);
        cudaEventCreateWithFlags(&s_evJoin, cudaEventDisableTiming);
    }
    if (!s_attrSet) {
        cudaFuncSetAttribute(gemm_mma_kernel,
                             cudaFuncAttributeMaxDynamicSharedMemorySize, GT_SMEM);
        s_attrSet = true;
    }

    // fork: side stream picks up from the capture/default stream
    cudaEventRecord(s_evFork, 0);
    cudaStreamWaitEvent(s_side, s_evFork, 0);

    // ---- chain B (side): CSR by dst ----
    zero_deg_kernel<<<(N + 255) / 256, 256, 0, s_side>>>(N);
    hist_kernel<<<(E + 255) / 256, 256, 0, s_side>>>(dst, E);
    scan_kernel<<<1, 1024, 0, s_side>>>(N);
    scatter_kernel<<<(E + 255) / 256, 256, 0, s_side>>>(dst, src, E);
    cudaEventRecord(s_evJoin, s_side);

    // ---- chain A (default stream): QKV projection ----
    prep_w_kernel<<<(INNER * DIM + 255) / 256, 256>>>(Wq, bq, Wk, bk, Wv, bv);
    conv_x_kernel<<<(N * (DIM / 4) + 255) / 256, 256>>>(x, N * (DIM / 4));
    dim3 ggrid((N + 127) / 128, INNER / 128);
    gemm_mma_kernel<<<ggrid, 256, GT_SMEM>>>(N);

    // join, then attention
    cudaStreamWaitEvent(0, s_evJoin, 0);
    attn_kernel<<<(N + 7) / 8, 256>>>(out, N);
}

// round 15
// speedup vs baseline: 1.3091x; 1.1634x over previous
#include <cuda_runtime.h>
#include <cuda_bf16.h>
#include <cuda_fp16.h>
#include <math.h>
#include <stdint.h>

#define DIM 256
#define INNER 768           // Q|K|V concatenated
#define HEADS 8
#define NMAX 50000
#define EMAX 800000

// ---------------- device scratch (static: allocation-free) --------------------
__device__ __half         g_q16[(size_t)NMAX * 256];    // q rows, fp16 (L2-resident gather set)
__device__ __half         g_v16[(size_t)NMAX * 256];    // v rows, fp16
__device__ float          g_k[(size_t)NMAX * 256];      // k rows, fp32 (sequential reads)
__device__ __nv_bfloat16  g_xh[(size_t)NMAX * DIM];
__device__ __nv_bfloat16  g_xl[(size_t)NMAX * DIM];
__device__ __nv_bfloat16  g_wth[INNER * DIM];            // W^T hi: [n][k]
__device__ __nv_bfloat16  g_wtl[INNER * DIM];            // W^T lo
__device__ float          g_bf[INNER];
__device__ __align__(16) int g_deg[NMAX];
__device__ int            g_off[NMAX + 1];
__device__ int            g_cur[NMAX];
__device__ int            g_sperm[EMAX];   // src node id, permuted into dst-CSR order

__device__ __forceinline__ uint32_t smem_u32(const void* p) {
    uint32_t a;
    asm("{ .reg .u64 t; cvta.to.shared.u64 t, %1; cvt.u32.u64 %0, t; }" : "=r"(a) : "l"(p));
    return a;
}

// 8 packed halves (uint4) -> two float4
__device__ __forceinline__ void h8_to_f8(uint4 r, float4& f0, float4& f1) {
    float2 a = __half22float2(*reinterpret_cast<__half2*>(&r.x));
    float2 b = __half22float2(*reinterpret_cast<__half2*>(&r.y));
    float2 c = __half22float2(*reinterpret_cast<__half2*>(&r.z));
    float2 d = __half22float2(*reinterpret_cast<__half2*>(&r.w));
    f0 = make_float4(a.x, a.y, b.x, b.y);
    f1 = make_float4(c.x, c.y, d.x, d.y);
}

// ---------------- prep: W^T hi/lo + bias --------------------------------------
__global__ void prep_w_kernel(const float* __restrict__ Wq, const float* __restrict__ bq,
                              const float* __restrict__ Wk, const float* __restrict__ bk,
                              const float* __restrict__ Wv, const float* __restrict__ bv) {
    int idx = blockIdx.x * blockDim.x + threadIdx.x;
    if (idx < INNER * DIM) {
        int n = idx >> 8, k = idx & 255;
        float w = (n < 256) ? Wq[k * 256 + n]
                : (n < 512) ? Wk[k * 256 + (n - 256)]
                            : Wv[k * 256 + (n - 512)];
        __nv_bfloat16 h = __float2bfloat16(w);
        __nv_bfloat16 l = __float2bfloat16(w - __bfloat162float(h));
        g_wth[idx] = h;   // layout [n][k] == idx
        g_wtl[idx] = l;
    }
    if (idx < INNER) {
        g_bf[idx] = (idx < 256) ? bq[idx] : (idx < 512) ? bk[idx - 256] : bv[idx - 512];
    }
}

__global__ void zero_deg_kernel(int n) {
    int i = blockIdx.x * blockDim.x + threadIdx.x;
    if (i < n) g_deg[i] = 0;
}

// ---------------- x -> bf16 hi/lo ----------------------------------------------
__global__ void conv_x_kernel(const float* __restrict__ x, int total4) {
    int i = blockIdx.x * blockDim.x + threadIdx.x;
    if (i >= total4) return;
    float4 v = ((const float4*)x)[i];
    float f[4] = {v.x, v.y, v.z, v.w};
    __nv_bfloat16 h[4], l[4];
#pragma unroll
    for (int j = 0; j < 4; ++j) {
        h[j] = __float2bfloat16(f[j]);
        l[j] = __float2bfloat16(f[j] - __bfloat162float(h[j]));
    }
    __nv_bfloat162* ph = (__nv_bfloat162*)g_xh + 2 * (size_t)i;
    __nv_bfloat162* pl = (__nv_bfloat162*)g_xl + 2 * (size_t)i;
    ph[0] = __halves2bfloat162(h[0], h[1]);
    ph[1] = __halves2bfloat162(h[2], h[3]);
    pl[0] = __halves2bfloat162(l[0], l[1]);
    pl[1] = __halves2bfloat162(l[2], l[3]);
}

// ---------------- mma.sync bf16 GEMM: [q16|k|v16] = x @ W + b -----------------
// CTA 128x128, BK=32, 8 warps (2x4), warp tile 64x32.
// Split fp32: C = Ah*Bh + Ah*Bl + Al*Bh.  cp.async 2-stage pipeline.
// Epilogue routes by n0 region: {0,128}->q16(fp16)  {256,384}->k(fp32)  {512,640}->v16(fp16)
#define BK 32
#define LDS 40            // smem row stride (bf16): 32 + 8 pad -> 80B
#define ARR_BYTES (128 * LDS * 2)      // 10240
#define OFF_AH 0
#define OFF_AL ARR_BYTES
#define OFF_BH (2 * ARR_BYTES)
#define OFF_BL (3 * ARR_BYTES)
#define STAGE_BYTES (4 * ARR_BYTES)    // 40960
#define GT_SMEM (2 * STAGE_BYTES)      // 81920

#define LDMX4(r0, r1, r2, r3, a)                                              \
    asm volatile("ldmatrix.sync.aligned.m8n8.x4.shared.b16 {%0,%1,%2,%3}, [%4];" \
        : "=r"(r0), "=r"(r1), "=r"(r2), "=r"(r3) : "r"(a))

#define MMA16816(c, A, B)                                                     \
    asm volatile("mma.sync.aligned.m16n8k16.row.col.f32.bf16.bf16.f32 "       \
        "{%0,%1,%2,%3}, {%4,%5,%6,%7}, {%8,%9}, {%0,%1,%2,%3};"               \
        : "+f"((c)[0]), "+f"((c)[1]), "+f"((c)[2]), "+f"((c)[3])              \
        : "r"((A)[0]), "r"((A)[1]), "r"((A)[2]), "r"((A)[3]),                 \
          "r"((B)[0]), "r"((B)[1]))

__device__ __forceinline__ void cp16(uint32_t d, const void* s, int sz) {
    asm volatile("cp.async.cg.shared.global [%0], [%1], 16, %2;"
                 :: "r"(d), "l"(s), "r"(sz));
}
#define CP_COMMIT() asm volatile("cp.async.commit_group;" ::: "memory")
#define CP_WAIT1()  asm volatile("cp.async.wait_group 1;" ::: "memory")

__global__ __launch_bounds__(256) void gemm_mma_kernel(int Nn) {
    extern __shared__ __align__(16) char dynsmem[];

    const int t = threadIdx.x;
    const int lane = t & 31;
    const int w = t >> 5;
    const int wm = (w & 1) * 64;     // warp row offset in CTA tile
    const int wn = (w >> 1) * 32;    // warp col offset
    const int m0 = blockIdx.x * 128;
    const int n0 = blockIdx.y * 128;
    const uint32_t sbase = smem_u32(dynsmem);

    float acc[4][4][4];
#pragma unroll
    for (int i = 0; i < 4; ++i)
#pragma unroll
        for (int j = 0; j < 4; ++j)
#pragma unroll
            for (int c = 0; c < 4; ++c) acc[i][j][c] = 0.f;

    // gmem->smem indices: 2 threads per row, 16 bf16 (32B = 2 cp.async) each
    const int ldr = t >> 1;               // 0..127
    const int ldc = (t & 1) * 16;         // 0 or 16
    const int s_byte = (ldr * LDS + ldc) * 2;
    const int asz = ((m0 + ldr) < Nn) ? 16 : 0;   // zero-fill M tail

    const __nv_bfloat16* gah = g_xh  + (size_t)(m0 + ldr) * DIM + ldc;
    const __nv_bfloat16* gal = g_xl  + (size_t)(m0 + ldr) * DIM + ldc;
    const __nv_bfloat16* gbh = g_wth + (size_t)(n0 + ldr) * DIM + ldc;
    const __nv_bfloat16* gbl = g_wtl + (size_t)(n0 + ldr) * DIM + ldc;

#define LOAD_STAGE(stg, k0) do {                                              \
        uint32_t sb_ = sbase + (stg) * STAGE_BYTES;                           \
        cp16(sb_ + OFF_AH + s_byte,      gah + (k0),     asz);                \
        cp16(sb_ + OFF_AH + s_byte + 16, gah + (k0) + 8, asz);                \
        cp16(sb_ + OFF_AL + s_byte,      gal + (k0),     asz);                \
        cp16(sb_ + OFF_AL + s_byte + 16, gal + (k0) + 8, asz);                \
        cp16(sb_ + OFF_BH + s_byte,      gbh + (k0),     16);                 \
        cp16(sb_ + OFF_BH + s_byte + 16, gbh + (k0) + 8, 16);                 \
        cp16(sb_ + OFF_BL + s_byte,      gbl + (k0),     16);                 \
        cp16(sb_ + OFF_BL + s_byte + 16, gbl + (k0) + 8, 16);                 \
    } while (0)

    LOAD_STAGE(0, 0);
    CP_COMMIT();

#pragma unroll 1
    for (int it = 0; it < DIM / BK; ++it) {
        if (it + 1 < DIM / BK) LOAD_STAGE((it + 1) & 1, (it + 1) * BK);
        CP_COMMIT();
        CP_WAIT1();
        __syncthreads();

        const uint32_t stg = sbase + (it & 1) * STAGE_BYTES;
        const uint32_t ah_b = stg + OFF_AH, al_b = stg + OFF_AL;
        const uint32_t bh_b = stg + OFF_BH, bl_b = stg + OFF_BL;

#pragma unroll
        for (int kk = 0; kk < BK; kk += 16) {
            // A fragments: 4 m-tiles x (hi, lo)
            uint32_t ah[4][4], al[4][4];
            {
                uint32_t aoff = ((wm + (lane & 15)) * LDS + kk + (lane >> 4) * 8) * 2;
#pragma unroll
                for (int mt = 0; mt < 4; ++mt) {
                    uint32_t adr = aoff + mt * 16 * LDS * 2;
                    LDMX4(ah[mt][0], ah[mt][1], ah[mt][2], ah[mt][3], ah_b + adr);
                    LDMX4(al[mt][0], al[mt][1], al[mt][2], al[mt][3], al_b + adr);
                }
            }
            // B fragments: 4 n-tiles x (hi, lo); x4 loads cover 2 n-tiles each
            uint32_t bh[4][2], bl[4][2];
            {
                int g = lane >> 3;
                uint32_t boff = ((wn + (g >> 1) * 8 + (lane & 7)) * LDS + kk + (g & 1) * 8) * 2;
#pragma unroll
                for (int p = 0; p < 2; ++p) {
                    uint32_t adr = boff + p * 16 * LDS * 2;
                    LDMX4(bh[2 * p][0], bh[2 * p][1], bh[2 * p + 1][0], bh[2 * p + 1][1], bh_b + adr);
                    LDMX4(bl[2 * p][0], bl[2 * p][1], bl[2 * p + 1][0], bl[2 * p + 1][1], bl_b + adr);
                }
            }
#pragma unroll
            for (int mt = 0; mt < 4; ++mt)
#pragma unroll
                for (int nt = 0; nt < 4; ++nt) {
                    MMA16816(acc[mt][nt], ah[mt], bh[nt]);
                    MMA16816(acc[mt][nt], ah[mt], bl[nt]);
                    MMA16816(acc[mt][nt], al[mt], bh[nt]);
                }
        }
        __syncthreads();
    }

    // epilogue: + bias, route to q16 (fp16) / k (fp32) / v16 (fp16)
    const int region = n0 >> 8;   // 0=q, 1=k, 2=v  (uniform per CTA)
#pragma unroll
    for (int mt = 0; mt < 4; ++mt) {
#pragma unroll
        for (int nt = 0; nt < 4; ++nt) {
            int row = m0 + wm + mt * 16 + (lane >> 2);
            int col = n0 + wn + nt * 8 + (lane & 3) * 2;   // global inner col
            int colr = col & 255;                           // col within region
            float2 bv = *(const float2*)(g_bf + col);
#pragma unroll
            for (int half_ = 0; half_ < 2; ++half_) {
                int r = row + half_ * 8;
                if (r < Nn) {
                    float ox = acc[mt][nt][2 * half_ + 0] + bv.x;
                    float oy = acc[mt][nt][2 * half_ + 1] + bv.y;
                    size_t off = (size_t)r * 256 + colr;
                    if (region == 1) {
                        *(float2*)(g_k + off) = make_float2(ox, oy);
                    } else {
                        __half2 hv = __floats2half2_rn(ox, oy);
                        __half2* dst = (region == 0) ? (__half2*)(g_q16 + off)
                                                     : (__half2*)(g_v16 + off);
                        *dst = hv;
                    }
                }
            }
        }
    }
}

// ---------------- CSR build ----------------------------------------------------
__global__ void hist_kernel(const int* __restrict__ dst, int E) {
    int e = blockIdx.x * blockDim.x + threadIdx.x;
    if (e < E) atomicAdd(&g_deg[dst[e]], 1);
}

// single-block shuffle-based exclusive scan: 1024 threads x 4 elements/tile
__global__ __launch_bounds__(1024) void scan_kernel(int n) {
    __shared__ int wsum[32];
    __shared__ int carry_s;
    const int t = threadIdx.x, lane = t & 31, wid = t >> 5;
    if (t == 0) carry_s = 0;
    __syncthreads();
    const int nTiles = (n + 4095) >> 12;
    for (int tile = 0; tile < nTiles; ++tile) {
        int idx = (tile << 12) + t * 4;
        int4 v = make_int4(0, 0, 0, 0);
        if (idx + 3 < n) v = *(const int4*)(g_deg + idx);
        else {
            if (idx + 0 < n) v.x = g_deg[idx];
            if (idx + 1 < n) v.y = g_deg[idx + 1];
            if (idx + 2 < n) v.z = g_deg[idx + 2];
        }
        int s = v.x + v.y + v.z + v.w;
        int incl = s;
#pragma unroll
        for (int d = 1; d < 32; d <<= 1) {
            int o = __shfl_up_sync(0xffffffffu, incl, d);
            if (lane >= d) incl += o;
        }
        if (lane == 31) wsum[wid] = incl;
        __syncthreads();
        if (wid == 0) {
            int ws = wsum[lane];
            int wincl = ws;
#pragma unroll
            for (int d = 1; d < 32; d <<= 1) {
                int o = __shfl_up_sync(0xffffffffu, wincl, d);
                if (lane >= d) wincl += o;
            }
            wsum[lane] = wincl - ws;   // exclusive warp prefix
        }
        __syncthreads();
        int excl = carry_s + wsum[wid] + (incl - s);
        int e0 = excl, e1 = e0 + v.x, e2 = e1 + v.y, e3 = e2 + v.z;
        if (idx + 0 < n) { g_off[idx + 0] = e0; g_cur[idx + 0] = e0; }
        if (idx + 1 < n) { g_off[idx + 1] = e1; g_cur[idx + 1] = e1; }
        if (idx + 2 < n) { g_off[idx + 2] = e2; g_cur[idx + 2] = e2; }
        if (idx + 3 < n) { g_off[idx + 3] = e3; g_cur[idx + 3] = e3; }
        __syncthreads();
        if (t == 1023) carry_s += wsum[31] + incl;
        __syncthreads();
    }
    if (t == 0) g_off[n] = carry_s;
}

// store src node id directly (kills one indirection in the attention hot loop)
__global__ void scatter_kernel(const int* __restrict__ dst, const int* __restrict__ src,
                               int E) {
    int e = blockIdx.x * blockDim.x + threadIdx.x;
    if (e < E) {
        int p = atomicAdd(&g_cur[dst[e]], 1);
        g_sperm[p] = src[e];
    }
}

// ---------------- single-pass online-softmax attention (2x unrolled, fp16) ----
// one warp per dst node; lane l owns output dims [8l,8l+8); head = l>>2.
// q/v gathered as fp16 (1 LDG.128 each): 51MB working set -> L2-resident.
__global__ __launch_bounds__(256) void attn_kernel(float* __restrict__ out, int n_nodes) {
    int gwarp = (blockIdx.x * blockDim.x + threadIdx.x) >> 5;
    int lane = threadIdx.x & 31;
    if (gwarp >= n_nodes) return;
    const int rs = g_off[gwarp];
    const int re = g_off[gwarp + 1];

    const float4* kp = (const float4*)(g_k + (size_t)gwarp * 256 + lane * 8);
    const float4 k0 = kp[0], k1 = kp[1];

    float m = -INFINITY, z = 0.f;
    float4 a0 = make_float4(0.f, 0.f, 0.f, 0.f);
    float4 a1 = make_float4(0.f, 0.f, 0.f, 0.f);

    int i = rs;
    // pairwise loop: 4 LDG.128 + 2 index loads in flight per pair
    for (; i + 1 < re; i += 2) {
        int s0 = __ldg(&g_sperm[i]);
        int s1 = __ldg(&g_sperm[i + 1]);
        uint4 qr0 = *(const uint4*)(g_q16 + (size_t)s0 * 256 + lane * 8);
        uint4 qr1 = *(const uint4*)(g_q16 + (size_t)s1 * 256 + lane * 8);
        uint4 vr0 = *(const uint4*)(g_v16 + (size_t)s0 * 256 + lane * 8);
        uint4 vr1 = *(const uint4*)(g_v16 + (size_t)s1 * 256 + lane * 8);

        float4 q00, q01, q10, q11, v00, v01, v10, v11;
        h8_to_f8(qr0, q00, q01);
        h8_to_f8(qr1, q10, q11);
        h8_to_f8(vr0, v00, v01);
        h8_to_f8(vr1, v10, v11);

        float p0 = q00.x * k0.x + q00.y * k0.y + q00.z * k0.z + q00.w * k0.w
                 + q01.x * k1.x + q01.y * k1.y + q01.z * k1.z + q01.w * k1.w;
        float p1 = q10.x * k0.x + q10.y * k0.y + q10.z * k0.z + q10.w * k0.w
                 + q11.x * k1.x + q11.y * k1.y + q11.z * k1.z + q11.w * k1.w;
        p0 += __shfl_xor_sync(0xffffffffu, p0, 1);
        p1 += __shfl_xor_sync(0xffffffffu, p1, 1);
        p0 += __shfl_xor_sync(0xffffffffu, p0, 2);
        p1 += __shfl_xor_sync(0xffffffffu, p1, 2);
        float sc0 = p0 * 0.17677669529663689f;   // 1/sqrt(32)
        float sc1 = p1 * 0.17677669529663689f;

        float nm = fmaxf(m, fmaxf(sc0, sc1));
        float scale = __expf(m - nm);            // first pair: exp(-inf)=0
        float w0 = __expf(sc0 - nm);
        float w1 = __expf(sc1 - nm);
        m = nm;
        z = fmaf(z, scale, w0 + w1);
        a0.x = fmaf(a0.x, scale, fmaf(v00.x, w0, v10.x * w1));
        a0.y = fmaf(a0.y, scale, fmaf(v00.y, w0, v10.y * w1));
        a0.z = fmaf(a0.z, scale, fmaf(v00.z, w0, v10.z * w1));
        a0.w = fmaf(a0.w, scale, fmaf(v00.w, w0, v10.w * w1));
        a1.x = fmaf(a1.x, scale, fmaf(v01.x, w0, v11.x * w1));
        a1.y = fmaf(a1.y, scale, fmaf(v01.y, w0, v11.y * w1));
        a1.z = fmaf(a1.z, scale, fmaf(v01.z, w0, v11.z * w1));
        a1.w = fmaf(a1.w, scale, fmaf(v01.w, w0, v11.w * w1));
    }
    // tail edge (odd degree)
    if (i < re) {
        int s = __ldg(&g_sperm[i]);
        uint4 qr = *(const uint4*)(g_q16 + (size_t)s * 256 + lane * 8);
        uint4 vr = *(const uint4*)(g_v16 + (size_t)s * 256 + lane * 8);
        float4 q0, q1, v0, v1;
        h8_to_f8(qr, q0, q1);
        h8_to_f8(vr, v0, v1);

        float p = q0.x * k0.x + q0.y * k0.y + q0.z * k0.z + q0.w * k0.w
                + q1.x * k1.x + q1.y * k1.y + q1.z * k1.z + q1.w * k1.w;
        p += __shfl_xor_sync(0xffffffffu, p, 1);
        p += __shfl_xor_sync(0xffffffffu, p, 2);
        float sc = p * 0.17677669529663689f;

        float nm = fmaxf(m, sc);
        float scale = __expf(m - nm);
        float wgt = __expf(sc - nm);
        m = nm;
        z = fmaf(z, scale, wgt);
        a0.x = fmaf(a0.x, scale, v0.x * wgt); a0.y = fmaf(a0.y, scale, v0.y * wgt);
        a0.z = fmaf(a0.z, scale, v0.z * wgt); a0.w = fmaf(a0.w, scale, v0.w * wgt);
        a1.x = fmaf(a1.x, scale, v1.x * wgt); a1.y = fmaf(a1.y, scale, v1.y * wgt);
        a1.z = fmaf(a1.z, scale, v1.z * wgt); a1.w = fmaf(a1.w, scale, v1.w * wgt);
    }

    float inv = 1.f / fmaxf(z, 1e-16f);
    float4* op = (float4*)(out + (size_t)gwarp * 256 + lane * 8);
    op[0] = make_float4(a0.x * inv, a0.y * inv, a0.z * inv, a0.w * inv);
    op[1] = make_float4(a1.x * inv, a1.y * inv, a1.z * inv, a1.w * inv);
}

// ---------------- launch: two-stream fork/join (R10 structure) -----------------
// Chain A (default stream): prep_w -> conv_x -> gemm        (feeds attn)
// Chain B (side stream):    zero_deg -> hist -> scan -> scatter (feeds attn)
extern "C" void kernel_launch(void* const* d_in, const int* in_sizes, int n_in,
                              void* d_out, int out_size) {
    const float* x  = (const float*)d_in[0];
    const float* Wq = (const float*)d_in[1];
    const float* bq = (const float*)d_in[2];
    const float* Wk = (const float*)d_in[3];
    const float* bk = (const float*)d_in[4];
    const float* Wv = (const float*)d_in[5];
    const float* bv = (const float*)d_in[6];
    const int* src  = (const int*)d_in[7];
    const int* dst  = (const int*)d_in[8];
    float* out = (float*)d_out;

    const int N = in_sizes[0] / DIM;
    const int E = in_sizes[7];

    // one-time host-side resources (no device memory involved)
    static cudaStream_t s_side = nullptr;
    static cudaEvent_t  s_evFork = nullptr, s_evJoin = nullptr;
    static bool s_attrSet = false;
    if (s_side == nullptr) {
        cudaStreamCreateWithFlags(&s_side, cudaStreamNonBlocking);
        cudaEventCreateWithFlags(&s_evFork, cudaEventDisableTiming);
        cudaEventCreateWithFlags(&s_evJoin, cudaEventDisableTiming);
    }
    if (!s_attrSet) {
        cudaFuncSetAttribute(gemm_mma_kernel,
                             cudaFuncAttributeMaxDynamicSharedMemorySize, GT_SMEM);
        s_attrSet = true;
    }

    // fork: side stream picks up from the capture/default stream
    cudaEventRecord(s_evFork, 0);
    cudaStreamWaitEvent(s_side, s_evFork, 0);

    // ---- chain B (side): CSR by dst ----
    zero_deg_kernel<<<(N + 255) / 256, 256, 0, s_side>>>(N);
    hist_kernel<<<(E + 255) / 256, 256, 0, s_side>>>(dst, E);
    scan_kernel<<<1, 1024, 0, s_side>>>(N);
    scatter_kernel<<<(E + 255) / 256, 256, 0, s_side>>>(dst, src, E);
    cudaEventRecord(s_evJoin, s_side);

    // ---- chain A (default stream): QKV projection ----
    prep_w_kernel<<<(INNER * DIM + 255) / 256, 256>>>(Wq, bq, Wk, bk, Wv, bv);
    conv_x_kernel<<<(N * (DIM / 4) + 255) / 256, 256>>>(x, N * (DIM / 4));
    dim3 ggrid((N + 127) / 128, INNER / 128);
    gemm_mma_kernel<<<ggrid, 256, GT_SMEM>>>(N);

    // join, then attention
    cudaStreamWaitEvent(0, s_evJoin, 0);
    attn_kernel<<<(N + 7) / 8, 256>>>(out, N);
}